// round 3
// baseline (speedup 1.0000x reference)
#include <cuda_runtime.h>

// LSTM: H=51, INPUT=1, OUTPUT=1, BATCH=4096, SEQ=999, future=0.
// Strategy: W_hh register-resident per thread (4 gate rows = 208 regs as f32x2
// pairs), h in shared (double buffered), c in a register. fma.rn.f32x2 doubles
// FMA throughput vs scalar FFMA. One kernel launch, graph-capturable.

#define H      51
#define NPAIR  26          // ceil(51/2) f32x2 pairs per gate row (padded)
#define BATCH  4096
#define SEQ    999
#define SLOT   56          // threads per batch element (k < 51 active)
#define BPC    2           // batch elements per CTA
#define TPB    (SLOT * BPC)

typedef unsigned long long ull;

__device__ __forceinline__ ull fma2(ull a, ull b, ull c) {
    ull d;
    asm("fma.rn.f32x2 %0, %1, %2, %3;" : "=l"(d) : "l"(a), "l"(b), "l"(c));
    return d;
}
__device__ __forceinline__ ull pk2(float x, float y) {
    ull r;
    asm("mov.b64 %0, {%1, %2};" : "=l"(r) : "f"(x), "f"(y));
    return r;
}
__device__ __forceinline__ float2 unpk(ull v) {
    float2 r;
    asm("mov.b64 {%0, %1}, %2;" : "=f"(r.x), "=f"(r.y) : "l"(v));
    return r;
}
// sigmoid via MUFU.EX2 + MUFU.RCP (abs err ~1e-6, safe vs 1e-3 threshold)
__device__ __forceinline__ float sigf(float x) {
    float e = __expf(-x);
    return __fdividef(1.0f, 1.0f + e);
}
// numerically safe fast tanh (no overflow for large |x|)
__device__ __forceinline__ float tanh_fast(float x) {
    float t = __expf(-2.0f * fabsf(x));
    float r = __fdividef(1.0f - t, 1.0f + t);
    return copysignf(r, x);
}

__global__ void __launch_bounds__(TPB)
lstm_kernel(const float* __restrict__ x,     // (B, SEQ, 1)
            const float* __restrict__ Wih,   // (204, 1)
            const float* __restrict__ Whh,   // (204, 51)
            const float* __restrict__ bih,   // (204,)
            const float* __restrict__ bhh,   // (204,)
            const float* __restrict__ Wfc,   // (1, 51)
            const float* __restrict__ bfc,   // (1,)
            float* __restrict__ out)         // (B, SEQ, 1)
{
    __shared__ ull   sh_h[2][BPC][NPAIR];   // double-buffered hidden state
    __shared__ float sh_y[2][BPC][64];      // double-buffered FC partials

    const int tid = threadIdx.x;
    const int bl  = tid / SLOT;
    const int k   = tid - bl * SLOT;
    const int b   = blockIdx.x * BPC + bl;
    const bool act = (k < H);

    // zero shared (h0 = 0, pads = 0)
    for (int i = tid; i < 2 * BPC * NPAIR; i += TPB) ((ull*)sh_h)[i] = 0ull;
    for (int i = tid; i < 2 * BPC * 64;    i += TPB) ((float*)sh_y)[i] = 0.0f;

    // ---- load W_hh rows for this thread's 4 gates into registers ----
    ull w0[NPAIR], w1[NPAIR], w2[NPAIR], w3[NPAIR];
    float bs0 = 0.f, bs1 = 0.f, bs2 = 0.f, bs3 = 0.f;
    float wi0 = 0.f, wi1 = 0.f, wi2 = 0.f, wi3 = 0.f;
    float wfck = 0.f, c = 0.f;

    if (act) {
        const float* r0 = Whh + (size_t)(k)         * H;   // i
        const float* r1 = Whh + (size_t)(k +     H) * H;   // f
        const float* r2 = Whh + (size_t)(k + 2 * H) * H;   // g
        const float* r3 = Whh + (size_t)(k + 3 * H) * H;   // o
#pragma unroll
        for (int m = 0; m < NPAIR - 1; m++) {
            w0[m] = pk2(r0[2 * m], r0[2 * m + 1]);
            w1[m] = pk2(r1[2 * m], r1[2 * m + 1]);
            w2[m] = pk2(r2[2 * m], r2[2 * m + 1]);
            w3[m] = pk2(r3[2 * m], r3[2 * m + 1]);
        }
        w0[NPAIR - 1] = pk2(r0[H - 1], 0.0f);
        w1[NPAIR - 1] = pk2(r1[H - 1], 0.0f);
        w2[NPAIR - 1] = pk2(r2[H - 1], 0.0f);
        w3[NPAIR - 1] = pk2(r3[H - 1], 0.0f);

        bs0 = bih[k]         + bhh[k];
        bs1 = bih[k + H]     + bhh[k + H];
        bs2 = bih[k + 2 * H] + bhh[k + 2 * H];
        bs3 = bih[k + 3 * H] + bhh[k + 3 * H];
        wi0 = Wih[k];
        wi1 = Wih[k + H];
        wi2 = Wih[k + 2 * H];
        wi3 = Wih[k + 3 * H];
        wfck = Wfc[k];
    }
    const float bfcv = bfc[0];
    const float* xrow = x + (size_t)b * SEQ;

    __syncthreads();

    float xv = xrow[0];
    for (int t = 0; t < SEQ; t++) {
        const int rb = t & 1;
        const int wb = rb ^ 1;
        // prefetch next x (hides L1/L2 latency behind gate compute)
        const float xn = (t + 1 < SEQ) ? xrow[t + 1] : 0.0f;

        if (act) {
            const ull* hb = sh_h[rb][bl];
            ull a0 = pk2(fmaf(xv, wi0, bs0), 0.0f);
            ull a1 = pk2(fmaf(xv, wi1, bs1), 0.0f);
            ull a2 = pk2(fmaf(xv, wi2, bs2), 0.0f);
            ull a3 = pk2(fmaf(xv, wi3, bs3), 0.0f);
#pragma unroll
            for (int m = 0; m < NPAIR; m++) {
                const ull hp = hb[m];          // broadcast LDS.64
                a0 = fma2(hp, w0[m], a0);
                a1 = fma2(hp, w1[m], a1);
                a2 = fma2(hp, w2[m], a2);
                a3 = fma2(hp, w3[m], a3);
            }
            const float2 u0 = unpk(a0), u1 = unpk(a1);
            const float2 u2 = unpk(a2), u3 = unpk(a3);
            const float gi = sigf(u0.x + u0.y);
            const float gf = sigf(u1.x + u1.y);
            const float gg = tanh_fast(u2.x + u2.y);
            const float go = sigf(u3.x + u3.y);
            c = fmaf(gf, c, gi * gg);
            const float h = go * tanh_fast(c);
            ((float*)sh_h[wb][bl])[k] = h;     // pad slot 51 stays 0
            sh_y[wb][bl][k] = h * wfck;
        }
        __syncthreads();

        // FC reduction for this step: warp 0 -> batch bl=0, warp 1 -> bl=1.
        // Reads sh_y[wb]; next write to sh_y[wb] happens only after the NEXT
        // barrier, so no race.
        if (tid < 64) {
            const int  w    = tid >> 5;
            const int  lane = tid & 31;
            const int  r    = lane & 15;
            const float* yp = sh_y[wb][w];
            float s = yp[r] + yp[r + 16] + yp[r + 32] + yp[r + 48];
            s += __shfl_down_sync(0xffffffffu, s, 8, 16);
            s += __shfl_down_sync(0xffffffffu, s, 4, 16);
            s += __shfl_down_sync(0xffffffffu, s, 2, 16);
            s += __shfl_down_sync(0xffffffffu, s, 1, 16);
            if (lane == 0)
                out[(size_t)(blockIdx.x * BPC + w) * SEQ + t] = s + bfcv;
        }
        xv = xn;
    }
}

extern "C" void kernel_launch(void* const* d_in, const int* in_sizes, int n_in,
                              void* d_out, int out_size) {
    const float* x_in = (const float*)d_in[0];
    const float* Wih  = (const float*)d_in[1];
    const float* Whh  = (const float*)d_in[2];
    const float* bih  = (const float*)d_in[3];
    const float* bhh  = (const float*)d_in[4];
    const float* Wfc  = (const float*)d_in[5];
    const float* bfc  = (const float*)d_in[6];
    // d_in[7] = future (static 0) — ignored.
    float* out = (float*)d_out;

    lstm_kernel<<<BATCH / BPC, TPB>>>(x_in, Wih, Whh, bih, bhh, Wfc, bfc, out);
    (void)in_sizes; (void)n_in; (void)out_size;
}